// round 15
// baseline (speedup 1.0000x reference)
#include <cuda_runtime.h>
#include <cuda_fp16.h>
#include <cstdint>
#include <cstddef>

// Problem constants
#define LQ 4096
#define EM 1024
#define HH 16
#define DD 64
#define CHK 128
#define NCH (LQ / CHK)       // 32
#define E3 (3 * EM)          // 3072
#define STATE (DD * DD + DD)

// -------------------- device scratch --------------------
__device__ float g_csum[(size_t)HH * NCH * STATE];
__device__ float g_cpre[(size_t)HH * NCH * STATE];
__device__ __half g_xh[(size_t)LQ * EM];       // x in fp16
__device__ __half g_wqh[(size_t)E3 * EM];      // qkv_w^T fp16 [3072][1024]
__device__ __half g_woh[(size_t)EM * EM];      // out_w^T fp16 [1024][1024]
__device__ __half g_qkvh[(size_t)LQ * E3];     // q'(elu+1), k'(elu+1), v in fp16
__device__ __half g_ah[(size_t)LQ * EM];       // attention output fp16

__device__ __forceinline__ float elup1(float x) {
    return x > 0.f ? x + 1.f : __expf(x);
}

__device__ __forceinline__ uint32_t smem_u32(const void* p) {
    uint32_t a;
    asm("{ .reg .u64 t; cvta.to.shared.u64 t, %1; cvt.u32.u64 %0, t; }" : "=r"(a) : "l"(p));
    return a;
}

__device__ __forceinline__ void ldsm_x4(uint32_t* r, uint32_t addr) {
    asm volatile("ldmatrix.sync.aligned.m8n8.x4.shared.b16 {%0,%1,%2,%3}, [%4];"
                 : "=r"(r[0]), "=r"(r[1]), "=r"(r[2]), "=r"(r[3]) : "r"(addr));
}

__device__ __forceinline__ void mma_f16(float* c, const uint32_t* a,
                                        uint32_t b0, uint32_t b1) {
    asm volatile(
        "mma.sync.aligned.m16n8k16.row.col.f32.f16.f16.f32 "
        "{%0,%1,%2,%3}, {%4,%5,%6,%7}, {%8,%9}, {%0,%1,%2,%3};"
        : "+f"(c[0]), "+f"(c[1]), "+f"(c[2]), "+f"(c[3])
        : "r"(a[0]), "r"(a[1]), "r"(a[2]), "r"(a[3]), "r"(b0), "r"(b1));
}

// 128B-row swizzle (8 x 16B chunks per row)
#define SWZ(r, c)  ((uint32_t)((r) * 128 + (((c) ^ ((r) & 7)) << 4)))
// 256B-row swizzle (16 x 16B chunks per row)
#define SWZ2(r, c) ((uint32_t)((r) * 256 + (((c) ^ ((r) & 15)) << 4)))

// ==================== prep kernels ====================
__global__ __launch_bounds__(256) void convert_x_kernel(const float* __restrict__ x) {
    size_t i = ((size_t)blockIdx.x * 256 + threadIdx.x) * 4;
    float4 v = *(const float4*)(x + i);
    __half h4[4] = { __float2half(v.x), __float2half(v.y),
                     __float2half(v.z), __float2half(v.w) };
    *(uint2*)(&g_xh[i]) = *(uint2*)h4;
}

__global__ __launch_bounds__(256) void tsplit_kernel(
    const float* __restrict__ w, __half* __restrict__ th, int K, int N)
{
    __shared__ float t[32][33];
    int bx = blockIdx.x * 32;  // N
    int by = blockIdx.y * 32;  // K
    int tx = threadIdx.x & 31, ty = threadIdx.x >> 5;
#pragma unroll
    for (int j = 0; j < 32; j += 8)
        t[ty + j][tx] = w[(size_t)(by + ty + j) * N + bx + tx];
    __syncthreads();
#pragma unroll
    for (int j = 0; j < 32; j += 8) {
        size_t o = (size_t)(bx + ty + j) * K + by + tx;
        th[o] = __float2half(t[tx][ty + j]);
    }
}

// ==================== HMMA fp16 GEMM ====================
// C = A[M][K] @ (B[N][K])^T + bias.
// CTA 128x256, BK=64, 512 threads (16 warps, warp tile 32x64),
// 3-stage cp.async pipeline, one __syncthreads per K-chunk.
// mode 0: fp32 out.  mode 1: fp16 out, elu+1 applied to cols < 2*EM (qkv).
#define STAGE_B 49152   // A tile 16KB + B tile 32KB

__global__ __launch_bounds__(512, 1) void gemm_mma_kernel(
    const __half* __restrict__ A, const __half* __restrict__ B,
    const float* __restrict__ bias, void* __restrict__ Cv,
    int M, int N, int K, int mode)
{
    extern __shared__ __align__(128) char smem[];   // 3 stages x 48KB
    const uint32_t sbase = smem_u32(smem);
    const int tid = threadIdx.x;
    const int lane = tid & 31;
    const int wid = tid >> 5;
    const int bm = blockIdx.y * 128, bn = blockIdx.x * 256;
    const int wm = (wid >> 2) * 32, wn = (wid & 3) * 64;   // 4x4 warps, 32x64 each

    float acc[2][8][4];
#pragma unroll
    for (int i = 0; i < 2; i++)
#pragma unroll
        for (int j = 0; j < 8; j++)
#pragma unroll
            for (int k = 0; k < 4; k++) acc[i][j][k] = 0.f;

    const int nch = K >> 6;

    auto issue = [&](int s, int k0) {
        uint32_t st = sbase + s * STAGE_B;
#pragma unroll
        for (int it = 0; it < 6; ++it) {
            int slot = tid + it * 512;            // 0..3071
            if (slot < 1024) {                    // A tile: 128x64
                int r = slot >> 3, c = slot & 7;
                const void* src = A + (size_t)(bm + r) * K + k0 + c * 8;
                uint32_t dst = st + SWZ(r, c);
                asm volatile("cp.async.cg.shared.global [%0], [%1], 16;"
                             :: "r"(dst), "l"(src) : "memory");
            } else {                              // B tile: 256x64
                int idx = slot - 1024;
                int r = idx >> 3, c = idx & 7;
                const void* src = B + (size_t)(bn + r) * K + k0 + c * 8;
                uint32_t dst = st + 16384 + SWZ(r, c);
                asm volatile("cp.async.cg.shared.global [%0], [%1], 16;"
                             :: "r"(dst), "l"(src) : "memory");
            }
        }
        asm volatile("cp.async.commit_group;" ::: "memory");
    };

    auto compute = [&](int s) {
        uint32_t st = sbase + s * STAGE_B;
#pragma unroll
        for (int ks = 0; ks < 4; ++ks) {
            uint32_t a[2][4];
#pragma unroll
            for (int mi = 0; mi < 2; ++mi) {
                int r = wm + mi * 16 + (lane & 15);
                int c = 2 * ks + (lane >> 4);
                ldsm_x4(a[mi], st + SWZ(r, c));
            }
            uint32_t b[4][4];
#pragma unroll
            for (int ng = 0; ng < 4; ++ng) {
                int r = wn + ng * 16 + ((lane >> 4) << 3) + (lane & 7);
                int c = 2 * ks + ((lane >> 3) & 1);
                ldsm_x4(b[ng], st + 16384 + SWZ(r, c));
            }
#pragma unroll
            for (int mi = 0; mi < 2; ++mi)
#pragma unroll
                for (int ni = 0; ni < 8; ++ni)
                    mma_f16(acc[mi][ni], a[mi],
                            b[ni >> 1][(ni & 1) * 2], b[ni >> 1][(ni & 1) * 2 + 1]);
        }
    };

    issue(0, 0);
    issue(1, 64);

    for (int ch = 0; ch < nch; ++ch) {
        asm volatile("cp.async.wait_group 1;" ::: "memory");
        __syncthreads();
        if (ch + 2 < nch) issue((ch + 2) % 3, (ch + 2) << 6);
        else asm volatile("cp.async.commit_group;" ::: "memory");
        compute(ch % 3);
    }

    if (mode == 0) {
        float* C = (float*)Cv;
#pragma unroll
        for (int mi = 0; mi < 2; ++mi) {
            int row0 = bm + wm + mi * 16 + (lane >> 2);
#pragma unroll
            for (int ni = 0; ni < 8; ++ni) {
                int col = bn + wn + ni * 8 + (lane & 3) * 2;
                float2 b2 = *(const float2*)&bias[col];
                float2 o0 = { acc[mi][ni][0] + b2.x, acc[mi][ni][1] + b2.y };
                float2 o1 = { acc[mi][ni][2] + b2.x, acc[mi][ni][3] + b2.y };
                *(float2*)&C[(size_t)row0 * N + col] = o0;
                *(float2*)&C[(size_t)(row0 + 8) * N + col] = o1;
            }
        }
    } else {
        __half* C = (__half*)Cv;
#pragma unroll
        for (int mi = 0; mi < 2; ++mi) {
            int row0 = bm + wm + mi * 16 + (lane >> 2);
#pragma unroll
            for (int ni = 0; ni < 8; ++ni) {
                int col = bn + wn + ni * 8 + (lane & 3) * 2;
                float2 b2 = *(const float2*)&bias[col];
                float v0 = acc[mi][ni][0] + b2.x, v1 = acc[mi][ni][1] + b2.y;
                float v2 = acc[mi][ni][2] + b2.x, v3 = acc[mi][ni][3] + b2.y;
                if (col < 2 * EM) {   // q,k columns: apply elu+1
                    v0 = elup1(v0); v1 = elup1(v1);
                    v2 = elup1(v2); v3 = elup1(v3);
                }
                __half h0[2] = { __float2half(v0), __float2half(v1) };
                __half h1[2] = { __float2half(v2), __float2half(v3) };
                *(uint32_t*)&C[(size_t)row0 * N + col] = *(uint32_t*)h0;
                *(uint32_t*)&C[(size_t)(row0 + 8) * N + col] = *(uint32_t*)h1;
            }
        }
    }
}

// ==================== phase A: HMMA per-chunk S = K'^T V, z = sum k' ====================
// S[d][e] = sum_i K'[i][d] * V[i][e]  == KT[64x128] @ (VT[64x128])^T
#define CS_KT 0            // [64][128] fp16, 256B-row swizzle  16384
#define CS_VT 16384        // [64][128] fp16                    16384
#define CS_STAGE 32768     // fp16 [128][72] padded stage       18432
#define CS_TOTAL 51200

// staged transpose helper: src rows [128][64] fp16 (gmem, row stride E3)
// -> dst [64 d][128 r] fp16 with SWZ2 rows.
__device__ __forceinline__ void transpose_to_swz2(
    char* smem, uint32_t dstoff, const __half* src, size_t rowstride, int tid)
{
    // pass 1: coalesced 16B reads -> padded stage [128][72] halves
#pragma unroll
    for (int it = 0; it < 4; ++it) {
        int slot = tid + it * 256;           // 0..1023
        int r = slot >> 3, cc = slot & 7;
        uint4 u = *(const uint4*)(src + (size_t)r * rowstride + cc * 8);
        *(uint4*)(smem + CS_STAGE + (r * 72 + cc * 8) * 2) = u;
    }
    __syncthreads();
    // pass 2: gather 8 r's per (d, rchunk), 16B swizzled store
#pragma unroll
    for (int it = 0; it < 4; ++it) {
        int slot = tid + it * 256;           // 0..1023
        int d = slot & 63, rc = slot >> 6;   // rc 0..15
        __half h8[8];
#pragma unroll
        for (int q = 0; q < 8; ++q)
            h8[q] = *(__half*)(smem + CS_STAGE + ((rc * 8 + q) * 72 + d) * 2);
        *(uint4*)(smem + dstoff + SWZ2(d, rc)) = *(uint4*)h8;
    }
}

__global__ __launch_bounds__(256) void chunk_sum_kernel() {
    extern __shared__ __align__(128) char smem[];
    const uint32_t sb = smem_u32(smem);

    const int tid = threadIdx.x;
    const int lane = tid & 31;
    const int wid = tid >> 5;
    const int h = blockIdx.x / NCH;
    const int c = blockIdx.x % NCH;
    const size_t rowbase = (size_t)(c * CHK) * E3 + h * DD;

    transpose_to_swz2(smem, CS_KT, g_qkvh + rowbase + EM, E3, tid);
    __syncthreads();
    transpose_to_swz2(smem, CS_VT, g_qkvh + rowbase + 2 * EM, E3, tid);
    __syncthreads();

    float* dstS = g_csum + (size_t)(h * NCH + c) * STATE;

    // HMMA GEMM: M=64 (d), N=64 (e), K=128 (i). 8 warps: 4x2 of 16x32 tiles.
    {
        const int wm = (wid >> 1) * 16, wn = (wid & 1) * 32;
        float acc[4][4];
#pragma unroll
        for (int j = 0; j < 4; j++)
#pragma unroll
            for (int k = 0; k < 4; k++) acc[j][k] = 0.f;

#pragma unroll
        for (int ks = 0; ks < 8; ++ks) {
            uint32_t a[4];
            {
                int r = wm + (lane & 15);
                int cc = 2 * ks + (lane >> 4);
                ldsm_x4(a, sb + CS_KT + SWZ2(r, cc));
            }
            uint32_t b[2][4];
#pragma unroll
            for (int ng = 0; ng < 2; ++ng) {
                int r = wn + ng * 16 + ((lane >> 4) << 3) + (lane & 7);
                int cc = 2 * ks + ((lane >> 3) & 1);
                ldsm_x4(b[ng], sb + CS_VT + SWZ2(r, cc));
            }
#pragma unroll
            for (int ni = 0; ni < 4; ++ni)
                mma_f16(acc[ni], a,
                        b[ni >> 1][(ni & 1) * 2], b[ni >> 1][(ni & 1) * 2 + 1]);
        }

        int row0 = wm + (lane >> 2);
#pragma unroll
        for (int ni = 0; ni < 4; ++ni) {
            int col = wn + ni * 8 + (lane & 3) * 2;
            *(float2*)&dstS[row0 * DD + col]       = *(float2*)&acc[ni][0];
            *(float2*)&dstS[(row0 + 8) * DD + col] = *(float2*)&acc[ni][2];
        }
    }

    // z[d] = sum_i K'[i][d] : row sums of KT via uint4 (swizzle -> conflict-free)
    if (tid < DD) {
        float z = 0.f;
#pragma unroll
        for (int cc = 0; cc < 16; ++cc) {
            uint4 u = *(uint4*)(smem + CS_KT + SWZ2(tid, cc));
            __half* hp = (__half*)&u;
#pragma unroll
            for (int q = 0; q < 8; ++q) z += __half2float(hp[q]);
        }
        dstS[DD * DD + tid] = z;
    }
}

// ==================== phase B: exclusive prefix over chunks ====================
#define PSLICE 17   // ceil(STATE/256)
__global__ __launch_bounds__(256) void prefix_kernel() {
    const int h = blockIdx.x / PSLICE;
    const int e = (blockIdx.x % PSLICE) * 256 + threadIdx.x;
    if (e >= STATE) return;
    float acc = 0.f;
#pragma unroll 4
    for (int c = 0; c < NCH; c++) {
        size_t idx = (size_t)(h * NCH + c) * STATE + e;
        g_cpre[idx] = acc;
        acc += g_csum[idx];
    }
}

// ==================== phase C: HMMA chunked causal attention ====================
// smem layout (bytes):
#define SA_QS   0          // [128][64] fp16 swizzled (128B rows)  16384
#define SA_KS   16384      // [128][64] fp16 swizzled              16384
#define SA_VT   32768      // [64][128] fp16 swizzled (256B rows)  16384
#define SA_SPT  49152      // [64][64]  fp16 swizzled (128B rows)   8192
#define SA_SS   57344      // [128][128] fp16 swizzled (256B rows) 32768
                           // (SS doubles as transpose stage pre-score)
#define SA_NSUM 90112      // [128] fp32                             512
#define SA_NRM  90624      // [128] fp32                             512
#define SA_ZP   91136      // [64]  fp32                             256
#define SA_TOTAL 91392

__global__ __launch_bounds__(256, 2) void chunk_attn_kernel() {
    extern __shared__ __align__(128) char smem[];
    const uint32_t sb = smem_u32(smem);
    float* nsum = (float*)(smem + SA_NSUM);
    float* nrm  = (float*)(smem + SA_NRM);
    float* zp   = (float*)(smem + SA_ZP);

    const int tid = threadIdx.x;
    const int lane = tid & 31;
    const int wid = tid >> 5;
    const int h = blockIdx.x / NCH;
    const int c = blockIdx.x % NCH;
    const size_t rowbase = (size_t)(c * CHK) * E3 + h * DD;

    // ---- async loads: Q', K' ----
#pragma unroll
    for (int it = 0; it < 8; ++it) {
        int slot = tid + it * 256;           // 0..2047
        int tsel = slot >> 10;               // 0:Q 1:K
        int idx = slot & 1023;
        int r = idx >> 3, cc = idx & 7;
        const void* src = g_qkvh + rowbase + (size_t)r * E3 + (tsel ? EM : 0) + cc * 8;
        uint32_t dst = sb + (tsel ? SA_KS : SA_QS) + SWZ(r, cc);
        asm volatile("cp.async.cg.shared.global [%0], [%1], 16;"
                     :: "r"(dst), "l"(src) : "memory");
    }
    asm volatile("cp.async.commit_group;" ::: "memory");

    // ---- V transpose via padded stage in SA_SS ----
    {
        // pass 1: coalesced 16B reads -> stage [128][72] halves
#pragma unroll
        for (int it = 0; it < 4; ++it) {
            int slot = tid + it * 256;
            int r = slot >> 3, cc = slot & 7;
            uint4 u = *(const uint4*)(g_qkvh + rowbase + (size_t)r * E3 + 2 * EM + cc * 8);
            *(uint4*)(smem + SA_SS + (r * 72 + cc * 8) * 2) = u;
        }
        __syncthreads();
        // pass 2: 16B swizzled stores to VT
#pragma unroll
        for (int it = 0; it < 4; ++it) {
            int slot = tid + it * 256;
            int d = slot & 63, rc = slot >> 6;
            __half h8[8];
#pragma unroll
            for (int q = 0; q < 8; ++q)
                h8[q] = *(__half*)(smem + SA_SS + ((rc * 8 + q) * 72 + d) * 2);
            *(uint4*)(smem + SA_VT + SWZ2(d, rc)) = *(uint4*)h8;
        }
    }
    __syncthreads();

    // ---- Sp transpose via padded fp32 stage in SA_SS ----
    const float* pre = g_cpre + (size_t)(h * NCH + c) * STATE;
    {
        // pass 1: coalesced float4 reads -> stage32 [64][68]
        float* stage32 = (float*)(smem + SA_SS);
#pragma unroll
        for (int it = 0; it < 4; ++it) {
            int slot = tid + it * 256;       // 0..1023 float4 units
            int i4 = slot * 4;
            int d = i4 >> 6, e = i4 & 63;
            float4 v = *(const float4*)(pre + i4);
            *(float4*)(stage32 + d * 68 + e) = v;
        }
        if (tid < DD) zp[tid] = pre[DD * DD + tid];
        __syncthreads();
        // pass 2: 16B swizzled fp16 stores to SpT[e][d]
#pragma unroll
        for (int it = 0; it < 2; ++it) {
            int slot = tid + it * 256;       // 0..511
            int e = slot & 63, cc = slot >> 6;   // cc 0..7
            __half h8[8];
#pragma unroll
            for (int q = 0; q < 8; ++q)
                h8[q] = __float2half(stage32[(cc * 8 + q) * 68 + e]);
            *(uint4*)(smem + SA_SPT + SWZ(e, cc)) = *(uint4*)h8;
        }
    }

    asm volatile("cp.async.wait_group 0;" ::: "memory");
    __syncthreads();

    // ---- nsum init: q' . zp  (row-wise uint4, conflict-free via swizzle) ----
    if (tid < CHK) {
        float s = 0.f;
#pragma unroll
        for (int cc = 0; cc < 8; ++cc) {
            uint4 u = *(uint4*)(smem + SA_QS + SWZ(tid, cc));
            __half* hp = (__half*)&u;
#pragma unroll
            for (int q = 0; q < 8; ++q)
                s += __half2float(hp[q]) * zp[cc * 8 + q];
        }
        nsum[tid] = s;
    }
    __syncthreads();

    // ---- score GEMM: S = Q' K'^T  (M=128, N=128, K=64) ----
    {
        const int wm = (wid >> 1) * 32, wn = (wid & 1) * 64;
        float acc[2][8][4];
#pragma unroll
        for (int i = 0; i < 2; i++)
#pragma unroll
            for (int j = 0; j < 8; j++)
#pragma unroll
                for (int k = 0; k < 4; k++) acc[i][j][k] = 0.f;

#pragma unroll
        for (int ks = 0; ks < 4; ++ks) {
            uint32_t a[2][4];
#pragma unroll
            for (int mi = 0; mi < 2; ++mi) {
                int r = wm + mi * 16 + (lane & 15);
                int cc = 2 * ks + (lane >> 4);
                ldsm_x4(a[mi], sb + SA_QS + SWZ(r, cc));
            }
            uint32_t b[4][4];
#pragma unroll
            for (int ng = 0; ng < 4; ++ng) {
                int r = wn + ng * 16 + ((lane >> 4) << 3) + (lane & 7);
                int cc = 2 * ks + ((lane >> 3) & 1);
                ldsm_x4(b[ng], sb + SA_KS + SWZ(r, cc));
            }
#pragma unroll
            for (int mi = 0; mi < 2; ++mi)
#pragma unroll
                for (int ni = 0; ni < 8; ++ni)
                    mma_f16(acc[mi][ni], a[mi],
                            b[ni >> 1][(ni & 1) * 2], b[ni >> 1][(ni & 1) * 2 + 1]);
        }

        // mask + store fp16 scores + norm partial sums
#pragma unroll
        for (int mi = 0; mi < 2; ++mi) {
            int i0 = wm + mi * 16 + (lane >> 2);
            int i1 = i0 + 8;
            float s0 = 0.f, s1 = 0.f;
#pragma unroll
            for (int ni = 0; ni < 8; ++ni) {
                int j0 = wn + ni * 8 + (lane & 3) * 2;
                float m00 = (j0     <= i0) ? acc[mi][ni][0] : 0.f;
                float m01 = (j0 + 1 <= i0) ? acc[mi][ni][1] : 0.f;
                float m10 = (j0     <= i1) ? acc[mi][ni][2] : 0.f;
                float m11 = (j0 + 1 <= i1) ? acc[mi][ni][3] : 0.f;
                s0 += m00 + m01;
                s1 += m10 + m11;
                __half p0[2] = { __float2half(m00), __float2half(m01) };
                __half p1[2] = { __float2half(m10), __float2half(m11) };
                *(uint32_t*)(smem + SA_SS + SWZ2(i0, j0 >> 3) + (j0 & 7) * 2) = *(uint32_t*)p0;
                *(uint32_t*)(smem + SA_SS + SWZ2(i1, j0 >> 3) + (j0 & 7) * 2) = *(uint32_t*)p1;
            }
            atomicAdd(&nsum[i0], s0);
            atomicAdd(&nsum[i1], s1);
        }
    }
    __syncthreads();

    if (tid < CHK) nrm[tid] = 1.f / (nsum[tid] + 1e-6f);

    // ---- output GEMM: O = Q' SpT^T + S V   (M=128, N=64) ----
    {
        const int wm = (wid >> 1) * 32, wn = (wid & 1) * 32;
        float acc[2][4][4];
#pragma unroll
        for (int i = 0; i < 2; i++)
#pragma unroll
            for (int j = 0; j < 4; j++)
#pragma unroll
                for (int k = 0; k < 4; k++) acc[i][j][k] = 0.f;

        // part A: Q'[128x64] x SpT[64x64]
#pragma unroll
        for (int ks = 0; ks < 4; ++ks) {
            uint32_t a[2][4];
#pragma unroll
            for (int mi = 0; mi < 2; ++mi) {
                int r = wm + mi * 16 + (lane & 15);
                int cc = 2 * ks + (lane >> 4);
                ldsm_x4(a[mi], sb + SA_QS + SWZ(r, cc));
            }
            uint32_t b[2][4];
#pragma unroll
            for (int ng = 0; ng < 2; ++ng) {
                int r = wn + ng * 16 + ((lane >> 4) << 3) + (lane & 7);
                int cc = 2 * ks + ((lane >> 3) & 1);
                ldsm_x4(b[ng], sb + SA_SPT + SWZ(r, cc));
            }
#pragma unroll
            for (int mi = 0; mi < 2; ++mi)
#pragma unroll
                for (int ni = 0; ni < 4; ++ni)
                    mma_f16(acc[mi][ni], a[mi],
                            b[ni >> 1][(ni & 1) * 2], b[ni >> 1][(ni & 1) * 2 + 1]);
        }
        // part B: S[128x128] x V^T tiles (VT is [64][128])
#pragma unroll
        for (int ks = 0; ks < 8; ++ks) {
            uint32_t a[2][4];
#pragma unroll
            for (int mi = 0; mi < 2; ++mi) {
                int r = wm + mi * 16 + (lane & 15);
                int cc = 2 * ks + (lane >> 4);
                ldsm_x4(a[mi], sb + SA_SS + SWZ2(r, cc));
            }
            uint32_t b[2][4];
#pragma unroll
            for (int ng = 0; ng < 2; ++ng) {
                int r = wn + ng * 16 + ((lane >> 4) << 3) + (lane & 7);
                int cc = 2 * ks + ((lane >> 3) & 1);
                ldsm_x4(b[ng], sb + SA_VT + SWZ2(r, cc));
            }
#pragma unroll
            for (int mi = 0; mi < 2; ++mi)
#pragma unroll
                for (int ni = 0; ni < 4; ++ni)
                    mma_f16(acc[mi][ni], a[mi],
                            b[ni >> 1][(ni & 1) * 2], b[ni >> 1][(ni & 1) * 2 + 1]);
        }
        __syncthreads();   // nrm visible

        // epilogue: scale by 1/norm, write fp16 to g_ah
#pragma unroll
        for (int mi = 0; mi < 2; ++mi) {
            int row0 = wm + mi * 16 + (lane >> 2);
            float n0 = nrm[row0], n1 = nrm[row0 + 8];
#pragma unroll
            for (int ni = 0; ni < 4; ++ni) {
                int col = wn + ni * 8 + (lane & 3) * 2;
                __half p0[2] = { __float2half(acc[mi][ni][0] * n0),
                                 __float2half(acc[mi][ni][1] * n0) };
                __half p1[2] = { __float2half(acc[mi][ni][2] * n1),
                                 __float2half(acc[mi][ni][3] * n1) };
                size_t o0 = (size_t)(c * CHK + row0) * EM + h * DD + col;
                size_t o1 = (size_t)(c * CHK + row0 + 8) * EM + h * DD + col;
                *(uint32_t*)&g_ah[o0] = *(uint32_t*)p0;
                *(uint32_t*)&g_ah[o1] = *(uint32_t*)p1;
            }
        }
    }
}

// ==================== launch ====================
extern "C" void kernel_launch(void* const* d_in, const int* in_sizes, int n_in,
                              void* d_out, int out_size) {
    const float* x      = (const float*)d_in[0];
    const float* qkv_w  = (const float*)d_in[1];
    const float* qkv_b  = (const float*)d_in[2];
    const float* out_w  = (const float*)d_in[3];
    const float* out_b  = (const float*)d_in[4];
    float* out = (float*)d_out;

    __half *p_xh, *p_wqh, *p_woh, *p_qkvh, *p_ah;
    cudaGetSymbolAddress((void**)&p_xh, g_xh);
    cudaGetSymbolAddress((void**)&p_wqh, g_wqh);
    cudaGetSymbolAddress((void**)&p_woh, g_woh);
    cudaGetSymbolAddress((void**)&p_qkvh, g_qkvh);
    cudaGetSymbolAddress((void**)&p_ah, g_ah);

    const int SMEM_G = 3 * STAGE_B;   // 144 KB
    cudaFuncSetAttribute(gemm_mma_kernel,
                         cudaFuncAttributeMaxDynamicSharedMemorySize, SMEM_G);
    cudaFuncSetAttribute(chunk_sum_kernel,
                         cudaFuncAttributeMaxDynamicSharedMemorySize, CS_TOTAL);
    cudaFuncSetAttribute(chunk_attn_kernel,
                         cudaFuncAttributeMaxDynamicSharedMemorySize, SA_TOTAL);

    // 0) operand preparation
    convert_x_kernel<<<(LQ * EM) / 1024, 256>>>(x);
    tsplit_kernel<<<dim3(E3 / 32, EM / 32), 256>>>(qkv_w, p_wqh, EM, E3);
    tsplit_kernel<<<dim3(EM / 32, EM / 32), 256>>>(out_w, p_woh, EM, EM);

    // 1) QKV projection -> fp16 with elu+1 fused on q,k columns (CTA 128x256)
    gemm_mma_kernel<<<dim3(E3 / 256, LQ / 128), 512, SMEM_G>>>(
        p_xh, p_wqh, qkv_b, p_qkvh, LQ, E3, EM, 1);

    // 2-4) chunked linear attention
    chunk_sum_kernel<<<HH * NCH, 256, CS_TOTAL>>>();
    prefix_kernel<<<HH * PSLICE, 256>>>();
    chunk_attn_kernel<<<HH * NCH, 256, SA_TOTAL>>>();

    // 5) output projection -> fp32 final output (CTA 128x256)
    gemm_mma_kernel<<<dim3(EM / 256, LQ / 128), 512, SMEM_G>>>(
        p_ah, p_woh, out_b, out, LQ, EM, EM, 0);
}

// round 16
// speedup vs baseline: 1.0134x; 1.0134x over previous
#include <cuda_runtime.h>
#include <cuda_fp16.h>
#include <cstdint>
#include <cstddef>

// Problem constants
#define LQ 4096
#define EM 1024
#define HH 16
#define DD 64
#define CHK 128
#define NCH (LQ / CHK)       // 32
#define E3 (3 * EM)          // 3072
#define STATE (DD * DD + DD)

// -------------------- device scratch --------------------
__device__ float g_csum[(size_t)HH * NCH * STATE];
__device__ float g_cpre[(size_t)HH * NCH * STATE];
__device__ __half g_xh[(size_t)LQ * EM];       // x in fp16
__device__ __half g_wqh[(size_t)E3 * EM];      // qkv_w^T fp16 [3072][1024]
__device__ __half g_woh[(size_t)EM * EM];      // out_w^T fp16 [1024][1024]
__device__ __half g_qkvh[(size_t)LQ * E3];     // q'(elu+1), k'(elu+1), v in fp16
__device__ __half g_ah[(size_t)LQ * EM];       // attention output fp16

__device__ __forceinline__ float elup1(float x) {
    return x > 0.f ? x + 1.f : __expf(x);
}

__device__ __forceinline__ uint32_t smem_u32(const void* p) {
    uint32_t a;
    asm("{ .reg .u64 t; cvta.to.shared.u64 t, %1; cvt.u32.u64 %0, t; }" : "=r"(a) : "l"(p));
    return a;
}

__device__ __forceinline__ void ldsm_x4(uint32_t* r, uint32_t addr) {
    asm volatile("ldmatrix.sync.aligned.m8n8.x4.shared.b16 {%0,%1,%2,%3}, [%4];"
                 : "=r"(r[0]), "=r"(r[1]), "=r"(r[2]), "=r"(r[3]) : "r"(addr));
}

__device__ __forceinline__ void mma_f16(float* c, const uint32_t* a,
                                        uint32_t b0, uint32_t b1) {
    asm volatile(
        "mma.sync.aligned.m16n8k16.row.col.f32.f16.f16.f32 "
        "{%0,%1,%2,%3}, {%4,%5,%6,%7}, {%8,%9}, {%0,%1,%2,%3};"
        : "+f"(c[0]), "+f"(c[1]), "+f"(c[2]), "+f"(c[3])
        : "r"(a[0]), "r"(a[1]), "r"(a[2]), "r"(a[3]), "r"(b0), "r"(b1));
}

// 128B-row swizzle (8 x 16B chunks per row)
#define SWZ(r, c)  ((uint32_t)((r) * 128 + (((c) ^ ((r) & 7)) << 4)))
// 256B-row swizzle (16 x 16B chunks per row)
#define SWZ2(r, c) ((uint32_t)((r) * 256 + (((c) ^ ((r) & 15)) << 4)))

// ==================== prep kernels ====================
__global__ __launch_bounds__(256) void convert_x_kernel(const float* __restrict__ x) {
    size_t i = ((size_t)blockIdx.x * 256 + threadIdx.x) * 4;
    float4 v = *(const float4*)(x + i);
    __half h4[4] = { __float2half(v.x), __float2half(v.y),
                     __float2half(v.z), __float2half(v.w) };
    *(uint2*)(&g_xh[i]) = *(uint2*)h4;
}

__global__ __launch_bounds__(256) void tsplit_kernel(
    const float* __restrict__ w, __half* __restrict__ th, int K, int N)
{
    __shared__ float t[32][33];
    int bx = blockIdx.x * 32;  // N
    int by = blockIdx.y * 32;  // K
    int tx = threadIdx.x & 31, ty = threadIdx.x >> 5;
#pragma unroll
    for (int j = 0; j < 32; j += 8)
        t[ty + j][tx] = w[(size_t)(by + ty + j) * N + bx + tx];
    __syncthreads();
#pragma unroll
    for (int j = 0; j < 32; j += 8) {
        size_t o = (size_t)(bx + ty + j) * K + by + tx;
        th[o] = __float2half(t[tx][ty + j]);
    }
}

// ==================== HMMA fp16 GEMM ====================
// C = A[M][K] @ (B[N][K])^T + bias.
// CTA 128x256, BK=64, 256 threads (8 warps, warp tile 64x64 -> MMA:ldsm = 4),
// 3-stage cp.async pipeline, one __syncthreads per K-chunk, 1 CTA/SM.
// mode 0: fp32 out.  mode 1: fp16 out, elu+1 applied to cols < 2*EM (qkv).
#define STAGE_B 49152   // A tile 16KB + B tile 32KB

__global__ __launch_bounds__(256, 1) void gemm_mma_kernel(
    const __half* __restrict__ A, const __half* __restrict__ B,
    const float* __restrict__ bias, void* __restrict__ Cv,
    int M, int N, int K, int mode)
{
    extern __shared__ __align__(128) char smem[];   // 3 stages x 48KB
    const uint32_t sbase = smem_u32(smem);
    const int tid = threadIdx.x;
    const int lane = tid & 31;
    const int wid = tid >> 5;
    const int bm = blockIdx.y * 128, bn = blockIdx.x * 256;
    const int wm = (wid >> 2) * 64, wn = (wid & 3) * 64;   // 2x4 warps, 64x64 each

    float acc[4][8][4];
#pragma unroll
    for (int i = 0; i < 4; i++)
#pragma unroll
        for (int j = 0; j < 8; j++)
#pragma unroll
            for (int k = 0; k < 4; k++) acc[i][j][k] = 0.f;

    const int nch = K >> 6;

    auto issue = [&](int s, int k0) {
        uint32_t st = sbase + s * STAGE_B;
#pragma unroll
        for (int it = 0; it < 12; ++it) {
            int slot = tid + it * 256;            // 0..3071
            if (slot < 1024) {                    // A tile: 128x64
                int r = slot >> 3, c = slot & 7;
                const void* src = A + (size_t)(bm + r) * K + k0 + c * 8;
                uint32_t dst = st + SWZ(r, c);
                asm volatile("cp.async.cg.shared.global [%0], [%1], 16;"
                             :: "r"(dst), "l"(src) : "memory");
            } else {                              // B tile: 256x64
                int idx = slot - 1024;
                int r = idx >> 3, c = idx & 7;
                const void* src = B + (size_t)(bn + r) * K + k0 + c * 8;
                uint32_t dst = st + 16384 + SWZ(r, c);
                asm volatile("cp.async.cg.shared.global [%0], [%1], 16;"
                             :: "r"(dst), "l"(src) : "memory");
            }
        }
        asm volatile("cp.async.commit_group;" ::: "memory");
    };

    auto compute = [&](int s) {
        uint32_t st = sbase + s * STAGE_B;
#pragma unroll
        for (int ks = 0; ks < 4; ++ks) {
            uint32_t a[4][4];
#pragma unroll
            for (int mi = 0; mi < 4; ++mi) {
                int r = wm + mi * 16 + (lane & 15);
                int c = 2 * ks + (lane >> 4);
                ldsm_x4(a[mi], st + SWZ(r, c));
            }
            uint32_t b[4][4];
#pragma unroll
            for (int ng = 0; ng < 4; ++ng) {
                int r = wn + ng * 16 + ((lane >> 4) << 3) + (lane & 7);
                int c = 2 * ks + ((lane >> 3) & 1);
                ldsm_x4(b[ng], st + 16384 + SWZ(r, c));
            }
#pragma unroll
            for (int mi = 0; mi < 4; ++mi)
#pragma unroll
                for (int ni = 0; ni < 8; ++ni)
                    mma_f16(acc[mi][ni], a[mi],
                            b[ni >> 1][(ni & 1) * 2], b[ni >> 1][(ni & 1) * 2 + 1]);
        }
    };

    issue(0, 0);
    issue(1, 64);

    for (int ch = 0; ch < nch; ++ch) {
        asm volatile("cp.async.wait_group 1;" ::: "memory");
        __syncthreads();
        if (ch + 2 < nch) issue((ch + 2) % 3, (ch + 2) << 6);
        else asm volatile("cp.async.commit_group;" ::: "memory");
        compute(ch % 3);
    }

    if (mode == 0) {
        float* C = (float*)Cv;
#pragma unroll
        for (int mi = 0; mi < 4; ++mi) {
            int row0 = bm + wm + mi * 16 + (lane >> 2);
#pragma unroll
            for (int ni = 0; ni < 8; ++ni) {
                int col = bn + wn + ni * 8 + (lane & 3) * 2;
                float2 b2 = *(const float2*)&bias[col];
                float2 o0 = { acc[mi][ni][0] + b2.x, acc[mi][ni][1] + b2.y };
                float2 o1 = { acc[mi][ni][2] + b2.x, acc[mi][ni][3] + b2.y };
                *(float2*)&C[(size_t)row0 * N + col] = o0;
                *(float2*)&C[(size_t)(row0 + 8) * N + col] = o1;
            }
        }
    } else {
        __half* C = (__half*)Cv;
#pragma unroll
        for (int mi = 0; mi < 4; ++mi) {
            int row0 = bm + wm + mi * 16 + (lane >> 2);
#pragma unroll
            for (int ni = 0; ni < 8; ++ni) {
                int col = bn + wn + ni * 8 + (lane & 3) * 2;
                float2 b2 = *(const float2*)&bias[col];
                float v0 = acc[mi][ni][0] + b2.x, v1 = acc[mi][ni][1] + b2.y;
                float v2 = acc[mi][ni][2] + b2.x, v3 = acc[mi][ni][3] + b2.y;
                if (col < 2 * EM) {   // q,k columns: apply elu+1
                    v0 = elup1(v0); v1 = elup1(v1);
                    v2 = elup1(v2); v3 = elup1(v3);
                }
                __half h0[2] = { __float2half(v0), __float2half(v1) };
                __half h1[2] = { __float2half(v2), __float2half(v3) };
                *(uint32_t*)&C[(size_t)row0 * N + col] = *(uint32_t*)h0;
                *(uint32_t*)&C[(size_t)(row0 + 8) * N + col] = *(uint32_t*)h1;
            }
        }
    }
}

// ==================== phase A: HMMA per-chunk S = K'^T V, z = sum k' ====================
// S[d][e] = sum_i K'[i][d] * V[i][e]  == KT[64x128] @ (VT[64x128])^T
#define CS_KT 0            // [64][128] fp16, 256B-row swizzle  16384
#define CS_VT 16384        // [64][128] fp16                    16384
#define CS_STAGE 32768     // fp16 [128][72] padded stage       18432
#define CS_TOTAL 51200

// staged transpose helper: src rows [128][64] fp16 (gmem, row stride E3)
// -> dst [64 d][128 r] fp16 with SWZ2 rows.
__device__ __forceinline__ void transpose_to_swz2(
    char* smem, uint32_t dstoff, const __half* src, size_t rowstride, int tid)
{
    // pass 1: coalesced 16B reads -> padded stage [128][72] halves
#pragma unroll
    for (int it = 0; it < 4; ++it) {
        int slot = tid + it * 256;           // 0..1023
        int r = slot >> 3, cc = slot & 7;
        uint4 u = *(const uint4*)(src + (size_t)r * rowstride + cc * 8);
        *(uint4*)(smem + CS_STAGE + (r * 72 + cc * 8) * 2) = u;
    }
    __syncthreads();
    // pass 2: gather 8 r's per (d, rchunk), 16B swizzled store
#pragma unroll
    for (int it = 0; it < 4; ++it) {
        int slot = tid + it * 256;           // 0..1023
        int d = slot & 63, rc = slot >> 6;   // rc 0..15
        __half h8[8];
#pragma unroll
        for (int q = 0; q < 8; ++q)
            h8[q] = *(__half*)(smem + CS_STAGE + ((rc * 8 + q) * 72 + d) * 2);
        *(uint4*)(smem + dstoff + SWZ2(d, rc)) = *(uint4*)h8;
    }
}

__global__ __launch_bounds__(256) void chunk_sum_kernel() {
    extern __shared__ __align__(128) char smem[];
    const uint32_t sb = smem_u32(smem);

    const int tid = threadIdx.x;
    const int lane = tid & 31;
    const int wid = tid >> 5;
    const int h = blockIdx.x / NCH;
    const int c = blockIdx.x % NCH;
    const size_t rowbase = (size_t)(c * CHK) * E3 + h * DD;

    transpose_to_swz2(smem, CS_KT, g_qkvh + rowbase + EM, E3, tid);
    __syncthreads();
    transpose_to_swz2(smem, CS_VT, g_qkvh + rowbase + 2 * EM, E3, tid);
    __syncthreads();

    float* dstS = g_csum + (size_t)(h * NCH + c) * STATE;

    // HMMA GEMM: M=64 (d), N=64 (e), K=128 (i). 8 warps: 4x2 of 16x32 tiles.
    {
        const int wm = (wid >> 1) * 16, wn = (wid & 1) * 32;
        float acc[4][4];
#pragma unroll
        for (int j = 0; j < 4; j++)
#pragma unroll
            for (int k = 0; k < 4; k++) acc[j][k] = 0.f;

#pragma unroll
        for (int ks = 0; ks < 8; ++ks) {
            uint32_t a[4];
            {
                int r = wm + (lane & 15);
                int cc = 2 * ks + (lane >> 4);
                ldsm_x4(a, sb + CS_KT + SWZ2(r, cc));
            }
            uint32_t b[2][4];
#pragma unroll
            for (int ng = 0; ng < 2; ++ng) {
                int r = wn + ng * 16 + ((lane >> 4) << 3) + (lane & 7);
                int cc = 2 * ks + ((lane >> 3) & 1);
                ldsm_x4(b[ng], sb + CS_VT + SWZ2(r, cc));
            }
#pragma unroll
            for (int ni = 0; ni < 4; ++ni)
                mma_f16(acc[ni], a,
                        b[ni >> 1][(ni & 1) * 2], b[ni >> 1][(ni & 1) * 2 + 1]);
        }

        int row0 = wm + (lane >> 2);
#pragma unroll
        for (int ni = 0; ni < 4; ++ni) {
            int col = wn + ni * 8 + (lane & 3) * 2;
            *(float2*)&dstS[row0 * DD + col]       = *(float2*)&acc[ni][0];
            *(float2*)&dstS[(row0 + 8) * DD + col] = *(float2*)&acc[ni][2];
        }
    }

    // z[d] = sum_i K'[i][d] : row sums of KT via uint4 (swizzle -> conflict-free)
    if (tid < DD) {
        float z = 0.f;
#pragma unroll
        for (int cc = 0; cc < 16; ++cc) {
            uint4 u = *(uint4*)(smem + CS_KT + SWZ2(tid, cc));
            __half* hp = (__half*)&u;
#pragma unroll
            for (int q = 0; q < 8; ++q) z += __half2float(hp[q]);
        }
        dstS[DD * DD + tid] = z;
    }
}

// ==================== phase B: exclusive prefix over chunks ====================
#define PSLICE 17   // ceil(STATE/256)
__global__ __launch_bounds__(256) void prefix_kernel() {
    const int h = blockIdx.x / PSLICE;
    const int e = (blockIdx.x % PSLICE) * 256 + threadIdx.x;
    if (e >= STATE) return;
    float acc = 0.f;
#pragma unroll 4
    for (int c = 0; c < NCH; c++) {
        size_t idx = (size_t)(h * NCH + c) * STATE + e;
        g_cpre[idx] = acc;
        acc += g_csum[idx];
    }
}

// ==================== phase C: HMMA chunked causal attention ====================
// smem layout (bytes):
#define SA_QS   0          // [128][64] fp16 swizzled (128B rows)  16384
#define SA_KS   16384      // [128][64] fp16 swizzled              16384
#define SA_VT   32768      // [64][128] fp16 swizzled (256B rows)  16384
#define SA_SPT  49152      // [64][64]  fp16 swizzled (128B rows)   8192
#define SA_SS   57344      // [128][128] fp16 swizzled (256B rows) 32768
                           // (SS doubles as transpose stage pre-score)
#define SA_NSUM 90112      // [128] fp32                             512
#define SA_NRM  90624      // [128] fp32                             512
#define SA_ZP   91136      // [64]  fp32                             256
#define SA_TOTAL 91392

__global__ __launch_bounds__(256, 2) void chunk_attn_kernel() {
    extern __shared__ __align__(128) char smem[];
    const uint32_t sb = smem_u32(smem);
    float* nsum = (float*)(smem + SA_NSUM);
    float* nrm  = (float*)(smem + SA_NRM);
    float* zp   = (float*)(smem + SA_ZP);

    const int tid = threadIdx.x;
    const int lane = tid & 31;
    const int wid = tid >> 5;
    const int h = blockIdx.x / NCH;
    const int c = blockIdx.x % NCH;
    const size_t rowbase = (size_t)(c * CHK) * E3 + h * DD;

    // ---- async loads: Q', K' ----
#pragma unroll
    for (int it = 0; it < 8; ++it) {
        int slot = tid + it * 256;           // 0..2047
        int tsel = slot >> 10;               // 0:Q 1:K
        int idx = slot & 1023;
        int r = idx >> 3, cc = idx & 7;
        const void* src = g_qkvh + rowbase + (size_t)r * E3 + (tsel ? EM : 0) + cc * 8;
        uint32_t dst = sb + (tsel ? SA_KS : SA_QS) + SWZ(r, cc);
        asm volatile("cp.async.cg.shared.global [%0], [%1], 16;"
                     :: "r"(dst), "l"(src) : "memory");
    }
    asm volatile("cp.async.commit_group;" ::: "memory");

    // ---- V transpose via padded stage in SA_SS ----
    {
        // pass 1: coalesced 16B reads -> stage [128][72] halves
#pragma unroll
        for (int it = 0; it < 4; ++it) {
            int slot = tid + it * 256;
            int r = slot >> 3, cc = slot & 7;
            uint4 u = *(const uint4*)(g_qkvh + rowbase + (size_t)r * E3 + 2 * EM + cc * 8);
            *(uint4*)(smem + SA_SS + (r * 72 + cc * 8) * 2) = u;
        }
        __syncthreads();
        // pass 2: 16B swizzled stores to VT
#pragma unroll
        for (int it = 0; it < 4; ++it) {
            int slot = tid + it * 256;
            int d = slot & 63, rc = slot >> 6;
            __half h8[8];
#pragma unroll
            for (int q = 0; q < 8; ++q)
                h8[q] = *(__half*)(smem + SA_SS + ((rc * 8 + q) * 72 + d) * 2);
            *(uint4*)(smem + SA_VT + SWZ2(d, rc)) = *(uint4*)h8;
        }
    }
    __syncthreads();

    // ---- Sp transpose via padded fp32 stage in SA_SS ----
    const float* pre = g_cpre + (size_t)(h * NCH + c) * STATE;
    {
        // pass 1: coalesced float4 reads -> stage32 [64][68]
        float* stage32 = (float*)(smem + SA_SS);
#pragma unroll
        for (int it = 0; it < 4; ++it) {
            int slot = tid + it * 256;       // 0..1023 float4 units
            int i4 = slot * 4;
            int d = i4 >> 6, e = i4 & 63;
            float4 v = *(const float4*)(pre + i4);
            *(float4*)(stage32 + d * 68 + e) = v;
        }
        if (tid < DD) zp[tid] = pre[DD * DD + tid];
        __syncthreads();
        // pass 2: 16B swizzled fp16 stores to SpT[e][d]
#pragma unroll
        for (int it = 0; it < 2; ++it) {
            int slot = tid + it * 256;       // 0..511
            int e = slot & 63, cc = slot >> 6;   // cc 0..7
            __half h8[8];
#pragma unroll
            for (int q = 0; q < 8; ++q)
                h8[q] = __float2half(stage32[(cc * 8 + q) * 68 + e]);
            *(uint4*)(smem + SA_SPT + SWZ(e, cc)) = *(uint4*)h8;
        }
    }

    asm volatile("cp.async.wait_group 0;" ::: "memory");
    __syncthreads();

    // ---- nsum init: q' . zp  (row-wise uint4, conflict-free via swizzle) ----
    if (tid < CHK) {
        float s = 0.f;
#pragma unroll
        for (int cc = 0; cc < 8; ++cc) {
            uint4 u = *(uint4*)(smem + SA_QS + SWZ(tid, cc));
            __half* hp = (__half*)&u;
#pragma unroll
            for (int q = 0; q < 8; ++q)
                s += __half2float(hp[q]) * zp[cc * 8 + q];
        }
        nsum[tid] = s;
    }
    __syncthreads();

    // ---- score GEMM: S = Q' K'^T  (M=128, N=128, K=64) ----
    {
        const int wm = (wid >> 1) * 32, wn = (wid & 1) * 64;
        float acc[2][8][4];
#pragma unroll
        for (int i = 0; i < 2; i++)
#pragma unroll
            for (int j = 0; j < 8; j++)
#pragma unroll
                for (int k = 0; k < 4; k++) acc[i][j][k] = 0.f;

#pragma unroll
        for (int ks = 0; ks < 4; ++ks) {
            uint32_t a[2][4];
#pragma unroll
            for (int mi = 0; mi < 2; ++mi) {
                int r = wm + mi * 16 + (lane & 15);
                int cc = 2 * ks + (lane >> 4);
                ldsm_x4(a[mi], sb + SA_QS + SWZ(r, cc));
            }
            uint32_t b[4][4];
#pragma unroll
            for (int ng = 0; ng < 4; ++ng) {
                int r = wn + ng * 16 + ((lane >> 4) << 3) + (lane & 7);
                int cc = 2 * ks + ((lane >> 3) & 1);
                ldsm_x4(b[ng], sb + SA_KS + SWZ(r, cc));
            }
#pragma unroll
            for (int mi = 0; mi < 2; ++mi)
#pragma unroll
                for (int ni = 0; ni < 8; ++ni)
                    mma_f16(acc[mi][ni], a[mi],
                            b[ni >> 1][(ni & 1) * 2], b[ni >> 1][(ni & 1) * 2 + 1]);
        }

        // mask + store fp16 scores + norm partial sums
#pragma unroll
        for (int mi = 0; mi < 2; ++mi) {
            int i0 = wm + mi * 16 + (lane >> 2);
            int i1 = i0 + 8;
            float s0 = 0.f, s1 = 0.f;
#pragma unroll
            for (int ni = 0; ni < 8; ++ni) {
                int j0 = wn + ni * 8 + (lane & 3) * 2;
                float m00 = (j0     <= i0) ? acc[mi][ni][0] : 0.f;
                float m01 = (j0 + 1 <= i0) ? acc[mi][ni][1] : 0.f;
                float m10 = (j0     <= i1) ? acc[mi][ni][2] : 0.f;
                float m11 = (j0 + 1 <= i1) ? acc[mi][ni][3] : 0.f;
                s0 += m00 + m01;
                s1 += m10 + m11;
                __half p0[2] = { __float2half(m00), __float2half(m01) };
                __half p1[2] = { __float2half(m10), __float2half(m11) };
                *(uint32_t*)(smem + SA_SS + SWZ2(i0, j0 >> 3) + (j0 & 7) * 2) = *(uint32_t*)p0;
                *(uint32_t*)(smem + SA_SS + SWZ2(i1, j0 >> 3) + (j0 & 7) * 2) = *(uint32_t*)p1;
            }
            atomicAdd(&nsum[i0], s0);
            atomicAdd(&nsum[i1], s1);
        }
    }
    __syncthreads();

    if (tid < CHK) nrm[tid] = 1.f / (nsum[tid] + 1e-6f);

    // ---- output GEMM: O = Q' SpT^T + S V   (M=128, N=64) ----
    {
        const int wm = (wid >> 1) * 32, wn = (wid & 1) * 32;
        float acc[2][4][4];
#pragma unroll
        for (int i = 0; i < 2; i++)
#pragma unroll
            for (int j = 0; j < 4; j++)
#pragma unroll
                for (int k = 0; k < 4; k++) acc[i][j][k] = 0.f;

        // part A: Q'[128x64] x SpT[64x64]
#pragma unroll
        for (int ks = 0; ks < 4; ++ks) {
            uint32_t a[2][4];
#pragma unroll
            for (int mi = 0; mi < 2; ++mi) {
                int r = wm + mi * 16 + (lane & 15);
                int cc = 2 * ks + (lane >> 4);
                ldsm_x4(a[mi], sb + SA_QS + SWZ(r, cc));
            }
            uint32_t b[2][4];
#pragma unroll
            for (int ng = 0; ng < 2; ++ng) {
                int r = wn + ng * 16 + ((lane >> 4) << 3) + (lane & 7);
                int cc = 2 * ks + ((lane >> 3) & 1);
                ldsm_x4(b[ng], sb + SA_SPT + SWZ(r, cc));
            }
#pragma unroll
            for (int mi = 0; mi < 2; ++mi)
#pragma unroll
                for (int ni = 0; ni < 4; ++ni)
                    mma_f16(acc[mi][ni], a[mi],
                            b[ni >> 1][(ni & 1) * 2], b[ni >> 1][(ni & 1) * 2 + 1]);
        }
        // part B: S[128x128] x V^T tiles (VT is [64][128])
#pragma unroll
        for (int ks = 0; ks < 8; ++ks) {
            uint32_t a[2][4];
#pragma unroll
            for (int mi = 0; mi < 2; ++mi) {
                int r = wm + mi * 16 + (lane & 15);
                int cc = 2 * ks + (lane >> 4);
                ldsm_x4(a[mi], sb + SA_SS + SWZ2(r, cc));
            }
            uint32_t b[2][4];
#pragma unroll
            for (int ng = 0; ng < 2; ++ng) {
                int r = wn + ng * 16 + ((lane >> 4) << 3) + (lane & 7);
                int cc = 2 * ks + ((lane >> 3) & 1);
                ldsm_x4(b[ng], sb + SA_VT + SWZ2(r, cc));
            }
#pragma unroll
            for (int mi = 0; mi < 2; ++mi)
#pragma unroll
                for (int ni = 0; ni < 4; ++ni)
                    mma_f16(acc[mi][ni], a[mi],
                            b[ni >> 1][(ni & 1) * 2], b[ni >> 1][(ni & 1) * 2 + 1]);
        }
        __syncthreads();   // nrm visible

        // epilogue: scale by 1/norm, write fp16 to g_ah
#pragma unroll
        for (int mi = 0; mi < 2; ++mi) {
            int row0 = wm + mi * 16 + (lane >> 2);
            float n0 = nrm[row0], n1 = nrm[row0 + 8];
#pragma unroll
            for (int ni = 0; ni < 4; ++ni) {
                int col = wn + ni * 8 + (lane & 3) * 2;
                __half p0[2] = { __float2half(acc[mi][ni][0] * n0),
                                 __float2half(acc[mi][ni][1] * n0) };
                __half p1[2] = { __float2half(acc[mi][ni][2] * n1),
                                 __float2half(acc[mi][ni][3] * n1) };
                size_t o0 = (size_t)(c * CHK + row0) * EM + h * DD + col;
                size_t o1 = (size_t)(c * CHK + row0 + 8) * EM + h * DD + col;
                *(uint32_t*)&g_ah[o0] = *(uint32_t*)p0;
                *(uint32_t*)&g_ah[o1] = *(uint32_t*)p1;
            }
        }
    }
}

// ==================== launch ====================
extern "C" void kernel_launch(void* const* d_in, const int* in_sizes, int n_in,
                              void* d_out, int out_size) {
    const float* x      = (const float*)d_in[0];
    const float* qkv_w  = (const float*)d_in[1];
    const float* qkv_b  = (const float*)d_in[2];
    const float* out_w  = (const float*)d_in[3];
    const float* out_b  = (const float*)d_in[4];
    float* out = (float*)d_out;

    __half *p_xh, *p_wqh, *p_woh, *p_qkvh, *p_ah;
    cudaGetSymbolAddress((void**)&p_xh, g_xh);
    cudaGetSymbolAddress((void**)&p_wqh, g_wqh);
    cudaGetSymbolAddress((void**)&p_woh, g_woh);
    cudaGetSymbolAddress((void**)&p_qkvh, g_qkvh);
    cudaGetSymbolAddress((void**)&p_ah, g_ah);

    const int SMEM_G = 3 * STAGE_B;   // 144 KB
    cudaFuncSetAttribute(gemm_mma_kernel,
                         cudaFuncAttributeMaxDynamicSharedMemorySize, SMEM_G);
    cudaFuncSetAttribute(chunk_sum_kernel,
                         cudaFuncAttributeMaxDynamicSharedMemorySize, CS_TOTAL);
    cudaFuncSetAttribute(chunk_attn_kernel,
                         cudaFuncAttributeMaxDynamicSharedMemorySize, SA_TOTAL);

    // 0) operand preparation
    convert_x_kernel<<<(LQ * EM) / 1024, 256>>>(x);
    tsplit_kernel<<<dim3(E3 / 32, EM / 32), 256>>>(qkv_w, p_wqh, EM, E3);
    tsplit_kernel<<<dim3(EM / 32, EM / 32), 256>>>(out_w, p_woh, EM, EM);

    // 1) QKV projection -> fp16 with elu+1 fused on q,k columns (CTA 128x256, 8 warps)
    gemm_mma_kernel<<<dim3(E3 / 256, LQ / 128), 256, SMEM_G>>>(
        p_xh, p_wqh, qkv_b, p_qkvh, LQ, E3, EM, 1);

    // 2-4) chunked linear attention
    chunk_sum_kernel<<<HH * NCH, 256, CS_TOTAL>>>();
    prefix_kernel<<<HH * PSLICE, 256>>>();
    chunk_attn_kernel<<<HH * NCH, 256, SA_TOTAL>>>();

    // 5) output projection -> fp32 final output (CTA 128x256, 8 warps)
    gemm_mma_kernel<<<dim3(EM / 256, LQ / 128), 256, SMEM_G>>>(
        p_ah, p_woh, out_b, out, LQ, EM, EM, 0);
}

// round 17
// speedup vs baseline: 1.0379x; 1.0242x over previous
#include <cuda_runtime.h>
#include <cuda_fp16.h>
#include <cstdint>
#include <cstddef>

// Problem constants
#define LQ 4096
#define EM 1024
#define HH 16
#define DD 64
#define CHK 128
#define NCH (LQ / CHK)       // 32
#define E3 (3 * EM)          // 3072
#define STATE (DD * DD + DD)

// -------------------- device scratch --------------------
__device__ float g_csum[(size_t)HH * NCH * STATE];
__device__ float g_cpre[(size_t)HH * NCH * STATE];
__device__ __half g_xh[(size_t)LQ * EM];       // x in fp16
__device__ __half g_wqh[(size_t)E3 * EM];      // qkv_w^T fp16 [3072][1024]
__device__ __half g_woh[(size_t)EM * EM];      // out_w^T fp16 [1024][1024]
__device__ __half g_qkvh[(size_t)LQ * E3];     // q'(elu+1), k'(elu+1), v in fp16
__device__ __half g_ah[(size_t)LQ * EM];       // attention output fp16

__device__ __forceinline__ float elup1(float x) {
    return x > 0.f ? x + 1.f : __expf(x);
}

__device__ __forceinline__ uint32_t smem_u32(const void* p) {
    uint32_t a;
    asm("{ .reg .u64 t; cvta.to.shared.u64 t, %1; cvt.u32.u64 %0, t; }" : "=r"(a) : "l"(p));
    return a;
}

__device__ __forceinline__ void ldsm_x4(uint32_t* r, uint32_t addr) {
    asm volatile("ldmatrix.sync.aligned.m8n8.x4.shared.b16 {%0,%1,%2,%3}, [%4];"
                 : "=r"(r[0]), "=r"(r[1]), "=r"(r[2]), "=r"(r[3]) : "r"(addr));
}

__device__ __forceinline__ void mma_f16(float* c, const uint32_t* a,
                                        uint32_t b0, uint32_t b1) {
    asm volatile(
        "mma.sync.aligned.m16n8k16.row.col.f32.f16.f16.f32 "
        "{%0,%1,%2,%3}, {%4,%5,%6,%7}, {%8,%9}, {%0,%1,%2,%3};"
        : "+f"(c[0]), "+f"(c[1]), "+f"(c[2]), "+f"(c[3])
        : "r"(a[0]), "r"(a[1]), "r"(a[2]), "r"(a[3]), "r"(b0), "r"(b1));
}

__device__ __forceinline__ uint32_t packh2(float a, float b) {
    __half2 h = __floats2half2_rn(a, b);
    return *(uint32_t*)&h;
}

// 128B-row swizzle (8 x 16B chunks per row)
#define SWZ(r, c)  ((uint32_t)((r) * 128 + (((c) ^ ((r) & 7)) << 4)))
// 256B-row swizzle (16 x 16B chunks per row)
#define SWZ2(r, c) ((uint32_t)((r) * 256 + (((c) ^ ((r) & 15)) << 4)))

// ==================== fused prep kernel ====================
// blocks [0, 3072): tsplit qkv_w; [3072, 4096): tsplit out_w; [4096, 8192): convert x
#define PREP_B1 3072
#define PREP_B2 4096
#define PREP_NB 8192

__global__ __launch_bounds__(256) void prep_kernel(
    const float* __restrict__ x, const float* __restrict__ qkv_w,
    const float* __restrict__ out_w,
    __half* __restrict__ wqh, __half* __restrict__ woh)
{
    int b = blockIdx.x;
    if (b >= PREP_B2) {
        size_t i = ((size_t)(b - PREP_B2) * 256 + threadIdx.x) * 4;
        float4 v = *(const float4*)(x + i);
        __half h4[4] = { __float2half(v.x), __float2half(v.y),
                         __float2half(v.z), __float2half(v.w) };
        *(uint2*)(&g_xh[i]) = *(uint2*)h4;
        return;
    }
    const float* w;
    __half* th;
    int N, bi;
    if (b < PREP_B1) { w = qkv_w; th = wqh; N = E3; bi = b; }
    else             { w = out_w; th = woh; N = EM; bi = b - PREP_B1; }
    const int K = EM;
    const int nbx = N / 32;
    int bx = (bi % nbx) * 32;   // N
    int by = (bi / nbx) * 32;   // K
    __shared__ float t[32][33];
    int tx = threadIdx.x & 31, ty = threadIdx.x >> 5;
#pragma unroll
    for (int j = 0; j < 32; j += 8)
        t[ty + j][tx] = w[(size_t)(by + ty + j) * N + bx + tx];
    __syncthreads();
#pragma unroll
    for (int j = 0; j < 32; j += 8) {
        size_t o = (size_t)(bx + ty + j) * K + by + tx;
        th[o] = __float2half(t[tx][ty + j]);
    }
}

// ==================== HMMA fp16 GEMM (R14 exact config) ====================
// C = A[M][K] @ (B[N][K])^T + bias.
// CTA 128x128, BK=64, 256 threads (8 warps, warp tile 32x64), 3-stage
// cp.async pipeline, one __syncthreads per K-chunk, 2 CTAs/SM.
// mode 0: fp32 out.  mode 1: fp16 out, elu+1 applied to cols < 2*EM (qkv).
#define STAGE_B 32768

__global__ __launch_bounds__(256, 2) void gemm_mma_kernel(
    const __half* __restrict__ A, const __half* __restrict__ B,
    const float* __restrict__ bias, void* __restrict__ Cv,
    int M, int N, int K, int mode)
{
    extern __shared__ __align__(128) char smem[];
    const uint32_t sbase = smem_u32(smem);
    const int tid = threadIdx.x;
    const int lane = tid & 31;
    const int wid = tid >> 5;
    const int bm = blockIdx.y * 128, bn = blockIdx.x * 128;
    const int wm = (wid >> 1) * 32, wn = (wid & 1) * 64;

    float acc[2][8][4];
#pragma unroll
    for (int i = 0; i < 2; i++)
#pragma unroll
        for (int j = 0; j < 8; j++)
#pragma unroll
            for (int k = 0; k < 4; k++) acc[i][j][k] = 0.f;

    const int nch = K >> 6;

    auto issue = [&](int s, int k0) {
        uint32_t st = sbase + s * STAGE_B;
#pragma unroll
        for (int it = 0; it < 8; ++it) {
            int slot = tid + it * 256;
            int tsel = slot >> 10;
            int idx = slot & 1023;
            int r = idx >> 3, c = idx & 7;
            const __half* base = tsel == 0 ? A : B;
            int row = (tsel == 0 ? bm : bn) + r;
            const void* src = base + (size_t)row * K + k0 + c * 8;
            uint32_t dst = st + tsel * 16384 + SWZ(r, c);
            asm volatile("cp.async.cg.shared.global [%0], [%1], 16;"
                         :: "r"(dst), "l"(src) : "memory");
        }
        asm volatile("cp.async.commit_group;" ::: "memory");
    };

    auto compute = [&](int s) {
        uint32_t st = sbase + s * STAGE_B;
#pragma unroll
        for (int ks = 0; ks < 4; ++ks) {
            uint32_t a[2][4];
#pragma unroll
            for (int mi = 0; mi < 2; ++mi) {
                int r = wm + mi * 16 + (lane & 15);
                int c = 2 * ks + (lane >> 4);
                ldsm_x4(a[mi], st + SWZ(r, c));
            }
            uint32_t b[4][4];
#pragma unroll
            for (int ng = 0; ng < 4; ++ng) {
                int r = wn + ng * 16 + ((lane >> 4) << 3) + (lane & 7);
                int c = 2 * ks + ((lane >> 3) & 1);
                ldsm_x4(b[ng], st + 16384 + SWZ(r, c));
            }
#pragma unroll
            for (int mi = 0; mi < 2; ++mi)
#pragma unroll
                for (int ni = 0; ni < 8; ++ni)
                    mma_f16(acc[mi][ni], a[mi],
                            b[ni >> 1][(ni & 1) * 2], b[ni >> 1][(ni & 1) * 2 + 1]);
        }
    };

    issue(0, 0);
    issue(1, 64);

    for (int ch = 0; ch < nch; ++ch) {
        asm volatile("cp.async.wait_group 1;" ::: "memory");
        __syncthreads();
        if (ch + 2 < nch) issue((ch + 2) % 3, (ch + 2) << 6);
        else asm volatile("cp.async.commit_group;" ::: "memory");
        compute(ch % 3);
    }

    if (mode == 0) {
        float* C = (float*)Cv;
#pragma unroll
        for (int mi = 0; mi < 2; ++mi) {
            int row0 = bm + wm + mi * 16 + (lane >> 2);
#pragma unroll
            for (int ni = 0; ni < 8; ++ni) {
                int col = bn + wn + ni * 8 + (lane & 3) * 2;
                float2 b2 = *(const float2*)&bias[col];
                float2 o0 = { acc[mi][ni][0] + b2.x, acc[mi][ni][1] + b2.y };
                float2 o1 = { acc[mi][ni][2] + b2.x, acc[mi][ni][3] + b2.y };
                *(float2*)&C[(size_t)row0 * N + col] = o0;
                *(float2*)&C[(size_t)(row0 + 8) * N + col] = o1;
            }
        }
    } else {
        __half* C = (__half*)Cv;
#pragma unroll
        for (int mi = 0; mi < 2; ++mi) {
            int row0 = bm + wm + mi * 16 + (lane >> 2);
#pragma unroll
            for (int ni = 0; ni < 8; ++ni) {
                int col = bn + wn + ni * 8 + (lane & 3) * 2;
                float2 b2 = *(const float2*)&bias[col];
                float v0 = acc[mi][ni][0] + b2.x, v1 = acc[mi][ni][1] + b2.y;
                float v2 = acc[mi][ni][2] + b2.x, v3 = acc[mi][ni][3] + b2.y;
                if (col < 2 * EM) {
                    v0 = elup1(v0); v1 = elup1(v1);
                    v2 = elup1(v2); v3 = elup1(v3);
                }
                __half h0[2] = { __float2half(v0), __float2half(v1) };
                __half h1[2] = { __float2half(v2), __float2half(v3) };
                *(uint32_t*)&C[(size_t)row0 * N + col] = *(uint32_t*)h0;
                *(uint32_t*)&C[(size_t)(row0 + 8) * N + col] = *(uint32_t*)h1;
            }
        }
    }
}

// ==================== phase A: HMMA per-chunk S = K'^T V, z = sum k' ====================
#define CS_KT 0
#define CS_VT 16384
#define CS_STAGE 32768
#define CS_TOTAL 51200

__device__ __forceinline__ void transpose_to_swz2(
    char* smem, uint32_t dstoff, const __half* src, size_t rowstride, int tid)
{
#pragma unroll
    for (int it = 0; it < 4; ++it) {
        int slot = tid + it * 256;
        int r = slot >> 3, cc = slot & 7;
        uint4 u = *(const uint4*)(src + (size_t)r * rowstride + cc * 8);
        *(uint4*)(smem + CS_STAGE + (r * 72 + cc * 8) * 2) = u;
    }
    __syncthreads();
#pragma unroll
    for (int it = 0; it < 4; ++it) {
        int slot = tid + it * 256;
        int d = slot & 63, rc = slot >> 6;
        __half h8[8];
#pragma unroll
        for (int q = 0; q < 8; ++q)
            h8[q] = *(__half*)(smem + CS_STAGE + ((rc * 8 + q) * 72 + d) * 2);
        *(uint4*)(smem + dstoff + SWZ2(d, rc)) = *(uint4*)h8;
    }
}

__global__ __launch_bounds__(256) void chunk_sum_kernel() {
    extern __shared__ __align__(128) char smem[];
    const uint32_t sb = smem_u32(smem);

    const int tid = threadIdx.x;
    const int lane = tid & 31;
    const int wid = tid >> 5;
    const int h = blockIdx.x / NCH;
    const int c = blockIdx.x % NCH;
    const size_t rowbase = (size_t)(c * CHK) * E3 + h * DD;

    transpose_to_swz2(smem, CS_KT, g_qkvh + rowbase + EM, E3, tid);
    __syncthreads();
    transpose_to_swz2(smem, CS_VT, g_qkvh + rowbase + 2 * EM, E3, tid);
    __syncthreads();

    float* dstS = g_csum + (size_t)(h * NCH + c) * STATE;

    {
        const int wm = (wid >> 1) * 16, wn = (wid & 1) * 32;
        float acc[4][4];
#pragma unroll
        for (int j = 0; j < 4; j++)
#pragma unroll
            for (int k = 0; k < 4; k++) acc[j][k] = 0.f;

#pragma unroll
        for (int ks = 0; ks < 8; ++ks) {
            uint32_t a[4];
            {
                int r = wm + (lane & 15);
                int cc = 2 * ks + (lane >> 4);
                ldsm_x4(a, sb + CS_KT + SWZ2(r, cc));
            }
            uint32_t b[2][4];
#pragma unroll
            for (int ng = 0; ng < 2; ++ng) {
                int r = wn + ng * 16 + ((lane >> 4) << 3) + (lane & 7);
                int cc = 2 * ks + ((lane >> 3) & 1);
                ldsm_x4(b[ng], sb + CS_VT + SWZ2(r, cc));
            }
#pragma unroll
            for (int ni = 0; ni < 4; ++ni)
                mma_f16(acc[ni], a,
                        b[ni >> 1][(ni & 1) * 2], b[ni >> 1][(ni & 1) * 2 + 1]);
        }

        int row0 = wm + (lane >> 2);
#pragma unroll
        for (int ni = 0; ni < 4; ++ni) {
            int col = wn + ni * 8 + (lane & 3) * 2;
            *(float2*)&dstS[row0 * DD + col]       = *(float2*)&acc[ni][0];
            *(float2*)&dstS[(row0 + 8) * DD + col] = *(float2*)&acc[ni][2];
        }
    }

    if (tid < DD) {
        float z = 0.f;
#pragma unroll
        for (int cc = 0; cc < 16; ++cc) {
            uint4 u = *(uint4*)(smem + CS_KT + SWZ2(tid, cc));
            __half* hp = (__half*)&u;
#pragma unroll
            for (int q = 0; q < 8; ++q) z += __half2float(hp[q]);
        }
        dstS[DD * DD + tid] = z;
    }
}

// ==================== phase B: exclusive prefix over chunks ====================
#define PSLICE 17
__global__ __launch_bounds__(256) void prefix_kernel() {
    const int h = blockIdx.x / PSLICE;
    const int e = (blockIdx.x % PSLICE) * 256 + threadIdx.x;
    if (e >= STATE) return;
    float acc = 0.f;
#pragma unroll 4
    for (int c = 0; c < NCH; c++) {
        size_t idx = (size_t)(h * NCH + c) * STATE + e;
        g_cpre[idx] = acc;
        acc += g_csum[idx];
    }
}

// ==================== phase C: HMMA chunked causal attention (register-S) ====================
// One warp owns 16 score rows (8 warps x 16 = 128). S never hits smem:
// score accumulators are masked+packed in registers into the A-fragment
// layout of the S.V MMA (m16n8 C-frag of 2 adjacent n-tiles == m16n8k16 A-frag).
// Row norms via in-register sums + quad shfl reduction.
// smem layout (bytes):
#define SA_QS   0          // [128][64] fp16 swizzled (128B rows)  16384
#define SA_KS   16384      // [128][64] fp16 swizzled              16384
#define SA_VT   32768      // [64][128] fp16 swizzled (256B rows)  16384
#define SA_SPT  49152      // [64][64]  fp16 swizzled (128B rows)   8192
#define SA_STG  57344      // transpose stage (18432)
#define SA_ZP   75776      // [64] fp32                              256
#define SA_TOTAL 76032

__global__ __launch_bounds__(256, 2) void chunk_attn_kernel() {
    extern __shared__ __align__(128) char smem[];
    const uint32_t sb = smem_u32(smem);
    float* zp = (float*)(smem + SA_ZP);

    const int tid = threadIdx.x;
    const int lane = tid & 31;
    const int wid = tid >> 5;
    const int h = blockIdx.x / NCH;
    const int c = blockIdx.x % NCH;
    const size_t rowbase = (size_t)(c * CHK) * E3 + h * DD;

    // ---- async loads: Q', K' ----
#pragma unroll
    for (int it = 0; it < 8; ++it) {
        int slot = tid + it * 256;
        int tsel = slot >> 10;
        int idx = slot & 1023;
        int r = idx >> 3, cc = idx & 7;
        const void* src = g_qkvh + rowbase + (size_t)r * E3 + (tsel ? EM : 0) + cc * 8;
        uint32_t dst = sb + (tsel ? SA_KS : SA_QS) + SWZ(r, cc);
        asm volatile("cp.async.cg.shared.global [%0], [%1], 16;"
                     :: "r"(dst), "l"(src) : "memory");
    }
    asm volatile("cp.async.commit_group;" ::: "memory");

    // ---- V transpose via padded stage ----
    {
#pragma unroll
        for (int it = 0; it < 4; ++it) {
            int slot = tid + it * 256;
            int r = slot >> 3, cc = slot & 7;
            uint4 u = *(const uint4*)(g_qkvh + rowbase + (size_t)r * E3 + 2 * EM + cc * 8);
            *(uint4*)(smem + SA_STG + (r * 72 + cc * 8) * 2) = u;
        }
        __syncthreads();
#pragma unroll
        for (int it = 0; it < 4; ++it) {
            int slot = tid + it * 256;
            int d = slot & 63, rc = slot >> 6;
            __half h8[8];
#pragma unroll
            for (int q = 0; q < 8; ++q)
                h8[q] = *(__half*)(smem + SA_STG + ((rc * 8 + q) * 72 + d) * 2);
            *(uint4*)(smem + SA_VT + SWZ2(d, rc)) = *(uint4*)h8;
        }
    }
    __syncthreads();

    // ---- Sp transpose via padded fp32 stage ----
    const float* pre = g_cpre + (size_t)(h * NCH + c) * STATE;
    {
        float* stage32 = (float*)(smem + SA_STG);
#pragma unroll
        for (int it = 0; it < 4; ++it) {
            int slot = tid + it * 256;
            int i4 = slot * 4;
            int d = i4 >> 6, e = i4 & 63;
            float4 v = *(const float4*)(pre + i4);
            *(float4*)(stage32 + d * 68 + e) = v;
        }
        if (tid < DD) zp[tid] = pre[DD * DD + tid];
        __syncthreads();
#pragma unroll
        for (int it = 0; it < 2; ++it) {
            int slot = tid + it * 256;
            int e = slot & 63, cc = slot >> 6;
            __half h8[8];
#pragma unroll
            for (int q = 0; q < 8; ++q)
                h8[q] = __float2half(stage32[(cc * 8 + q) * 68 + e]);
            *(uint4*)(smem + SA_SPT + SWZ(e, cc)) = *(uint4*)h8;
        }
    }

    asm volatile("cp.async.wait_group 0;" ::: "memory");
    __syncthreads();

    const int wm = wid * 16;            // this warp's 16 score rows
    const int r0 = wm + (lane >> 2);    // local row index
    const int r1 = r0 + 8;

    // ---- score GEMM: S[16x128] = Q'[wm..wm+16) x K'^T ----
    float accs[16][4];
#pragma unroll
    for (int n = 0; n < 16; ++n)
#pragma unroll
        for (int k = 0; k < 4; ++k) accs[n][k] = 0.f;

#pragma unroll
    for (int ks = 0; ks < 4; ++ks) {
        uint32_t a[4];
        {
            int r = wm + (lane & 15);
            int cc = 2 * ks + (lane >> 4);
            ldsm_x4(a, sb + SA_QS + SWZ(r, cc));
        }
#pragma unroll
        for (int half = 0; half < 2; ++half) {
            uint32_t b[4][4];
#pragma unroll
            for (int ng = 0; ng < 4; ++ng) {
                int r = half * 64 + ng * 16 + ((lane >> 4) << 3) + (lane & 7);
                int cc = 2 * ks + ((lane >> 3) & 1);
                ldsm_x4(b[ng], sb + SA_KS + SWZ(r, cc));
            }
#pragma unroll
            for (int nt = 0; nt < 8; ++nt)
                mma_f16(accs[half * 8 + nt], a,
                        b[nt >> 1][(nt & 1) * 2], b[nt >> 1][(nt & 1) * 2 + 1]);
        }
    }

    // ---- mask + pack to A-frags (register S) + row sums ----
    uint32_t sa[8][4];
    float s0 = 0.f, s1 = 0.f;
#pragma unroll
    for (int n = 0; n < 16; ++n) {
        int col0 = n * 8 + (lane & 3) * 2;
        float m0 = (col0     <= r0) ? accs[n][0] : 0.f;
        float m1 = (col0 + 1 <= r0) ? accs[n][1] : 0.f;
        float m2 = (col0     <= r1) ? accs[n][2] : 0.f;
        float m3 = (col0 + 1 <= r1) ? accs[n][3] : 0.f;
        s0 += m0 + m1;
        s1 += m2 + m3;
        int t = n >> 1;
        if ((n & 1) == 0) { sa[t][0] = packh2(m0, m1); sa[t][1] = packh2(m2, m3); }
        else              { sa[t][2] = packh2(m0, m1); sa[t][3] = packh2(m2, m3); }
    }
    // q'.zp partials over this thread's d-range
    {
        int ccb = (lane & 3) * 2;
#pragma unroll
        for (int q = 0; q < 2; ++q) {
            uint4 u0 = *(uint4*)(smem + SA_QS + SWZ(r0, ccb + q));
            uint4 u1 = *(uint4*)(smem + SA_QS + SWZ(r1, ccb + q));
            __half* h0 = (__half*)&u0;
            __half* h1 = (__half*)&u1;
#pragma unroll
            for (int e = 0; e < 8; ++e) {
                float z = zp[(ccb + q) * 8 + e];
                s0 += __half2float(h0[e]) * z;
                s1 += __half2float(h1[e]) * z;
            }
        }
    }
    // quad reduction (lanes 4k..4k+3 share rows r0, r1)
    s0 += __shfl_xor_sync(0xffffffffu, s0, 1);
    s0 += __shfl_xor_sync(0xffffffffu, s0, 2);
    s1 += __shfl_xor_sync(0xffffffffu, s1, 1);
    s1 += __shfl_xor_sync(0xffffffffu, s1, 2);
    const float nrm0 = 1.f / (s0 + 1e-6f);
    const float nrm1 = 1.f / (s1 + 1e-6f);

    // ---- output GEMM: O[16x64] = Q' x SpT^T + S x V ----
    float acco[8][4];
#pragma unroll
    for (int n = 0; n < 8; ++n)
#pragma unroll
        for (int k = 0; k < 4; ++k) acco[n][k] = 0.f;

    // part A: Q'[16x64] x SpT[64x64]
#pragma unroll
    for (int ks = 0; ks < 4; ++ks) {
        uint32_t a[4];
        {
            int r = wm + (lane & 15);
            int cc = 2 * ks + (lane >> 4);
            ldsm_x4(a, sb + SA_QS + SWZ(r, cc));
        }
        uint32_t b[4][4];
#pragma unroll
        for (int ng = 0; ng < 4; ++ng) {
            int r = ng * 16 + ((lane >> 4) << 3) + (lane & 7);
            int cc = 2 * ks + ((lane >> 3) & 1);
            ldsm_x4(b[ng], sb + SA_SPT + SWZ(r, cc));
        }
#pragma unroll
        for (int n = 0; n < 8; ++n)
            mma_f16(acco[n], a,
                    b[n >> 1][(n & 1) * 2], b[n >> 1][(n & 1) * 2 + 1]);
    }
    // part B: S[16x128] x V (B = VT[e][j]), A from registers
#pragma unroll
    for (int t = 0; t < 8; ++t) {
        uint32_t b[4][4];
#pragma unroll
        for (int ng = 0; ng < 4; ++ng) {
            int r = ng * 16 + ((lane >> 4) << 3) + (lane & 7);
            int cc = 2 * t + ((lane >> 3) & 1);
            ldsm_x4(b[ng], sb + SA_VT + SWZ2(r, cc));
        }
#pragma unroll
        for (int n = 0; n < 8; ++n)
            mma_f16(acco[n], sa[t],
                    b[n >> 1][(n & 1) * 2], b[n >> 1][(n & 1) * 2 + 1]);
    }

    // ---- epilogue: scale by 1/norm, write fp16 to g_ah ----
#pragma unroll
    for (int n = 0; n < 8; ++n) {
        int col = n * 8 + (lane & 3) * 2;
        uint32_t p0 = packh2(acco[n][0] * nrm0, acco[n][1] * nrm0);
        uint32_t p1 = packh2(acco[n][2] * nrm1, acco[n][3] * nrm1);
        size_t o0 = (size_t)(c * CHK + r0) * EM + h * DD + col;
        size_t o1 = (size_t)(c * CHK + r1) * EM + h * DD + col;
        *(uint32_t*)&g_ah[o0] = p0;
        *(uint32_t*)&g_ah[o1] = p1;
    }
}

// ==================== launch ====================
extern "C" void kernel_launch(void* const* d_in, const int* in_sizes, int n_in,
                              void* d_out, int out_size) {
    const float* x      = (const float*)d_in[0];
    const float* qkv_w  = (const float*)d_in[1];
    const float* qkv_b  = (const float*)d_in[2];
    const float* out_w  = (const float*)d_in[3];
    const float* out_b  = (const float*)d_in[4];
    float* out = (float*)d_out;

    __half *p_xh, *p_wqh, *p_woh, *p_qkvh, *p_ah;
    cudaGetSymbolAddress((void**)&p_xh, g_xh);
    cudaGetSymbolAddress((void**)&p_wqh, g_wqh);
    cudaGetSymbolAddress((void**)&p_woh, g_woh);
    cudaGetSymbolAddress((void**)&p_qkvh, g_qkvh);
    cudaGetSymbolAddress((void**)&p_ah, g_ah);

    const int SMEM_G = 3 * STAGE_B;   // 96 KB
    cudaFuncSetAttribute(gemm_mma_kernel,
                         cudaFuncAttributeMaxDynamicSharedMemorySize, SMEM_G);
    cudaFuncSetAttribute(chunk_sum_kernel,
                         cudaFuncAttributeMaxDynamicSharedMemorySize, CS_TOTAL);
    cudaFuncSetAttribute(chunk_attn_kernel,
                         cudaFuncAttributeMaxDynamicSharedMemorySize, SA_TOTAL);

    // 0) fused operand preparation
    prep_kernel<<<PREP_NB, 256>>>(x, qkv_w, out_w, p_wqh, p_woh);

    // 1) QKV projection -> fp16 with elu+1 fused on q,k columns
    gemm_mma_kernel<<<dim3(E3 / 128, LQ / 128), 256, SMEM_G>>>(
        p_xh, p_wqh, qkv_b, p_qkvh, LQ, E3, EM, 1);

    // 2-4) chunked linear attention
    chunk_sum_kernel<<<HH * NCH, 256, CS_TOTAL>>>();
    prefix_kernel<<<HH * PSLICE, 256>>>();
    chunk_attn_kernel<<<HH * NCH, 256, SA_TOTAL>>>();

    // 5) output projection -> fp32 final output
    gemm_mma_kernel<<<dim3(EM / 128, LQ / 128), 256, SMEM_G>>>(
        p_ah, p_woh, out_b, out, LQ, EM, EM, 0);
}